// round 8
// baseline (speedup 1.0000x reference)
#include <cuda_runtime.h>

typedef unsigned long long u64;

#define TPB 256
// element strides in u64 units; 21 mod 16 = 5 (coprime 16) and 17 mod 16 = 1
// -> conflict-free LDS.64 across lanes
#define STRIDE10 21   // 20 u64 data (40 floats) + 1 pad
#define STRIDE8  17   // 16 u64 data (32 floats) + 1 pad

// ---- packed f32x2 helpers ----
__device__ __forceinline__ u64 pk2(float lo, float hi) {
    u64 r; asm("mov.b64 %0,{%1,%2};" : "=l"(r) : "f"(lo), "f"(hi)); return r;
}
__device__ __forceinline__ float2 unpk(u64 v) {
    float2 f; asm("mov.b64 {%0,%1},%2;" : "=f"(f.x), "=f"(f.y) : "l"(v)); return f;
}
__device__ __forceinline__ u64 fma2(u64 a, u64 b, u64 c) {
    u64 d; asm("fma.rn.f32x2 %0,%1,%2,%3;" : "=l"(d) : "l"(a), "l"(b), "l"(c)); return d;
}
__device__ __forceinline__ u64 relu2(u64 v) {
    float2 f = unpk(v);
    return pk2(fmaxf(f.x, 0.f), fmaxf(f.y, 0.f));
}

// ---- shared weight layout (float2-duplicated), offsets in u64 units ----
#define O_EW1 0
#define O_EB1 100
#define O_EW2 110
#define O_EB2 210
#define O_EW3 220
#define O_EB3 230
#define O_XW1 231
#define O_XB1 295
#define O_XW2 303
#define O_XB2 367
#define O_XW3 375
#define O_XB3 383
#define O_CW1 384
#define O_CB1 484
#define O_CW2 494
#define O_CB2 594
#define O_CW3 604
#define O_CB3 614
#define O_NW  615
#define O_NB  616
#define NWTS  617

// 3-layer MLP over 4 slices as two f32x2 pairs, interleaved so every weight
// LDS.64 is reused by both pairs. xe points at this element's staged u64 data:
// u64 index i*2+p holds {slice 2p, slice 2p+1} for input feature i.
template <int D>
__device__ __forceinline__ float mlp_sum4(const u64* __restrict__ xe,
                                          const u64* __restrict__ w1, const u64* __restrict__ b1,
                                          const u64* __restrict__ w2, const u64* __restrict__ b2,
                                          const u64* __restrict__ w3, const u64* __restrict__ b3) {
    u64 x0[D], x1[D], h0[D], h1[D];
#pragma unroll
    for (int i = 0; i < D; i++) { x0[i] = xe[i * 2]; x1[i] = xe[i * 2 + 1]; }
    // layer 1 + relu
#pragma unroll
    for (int o = 0; o < D; o++) {
        u64 b = b1[o], a0 = b, a1 = b;
#pragma unroll
        for (int i = 0; i < D; i++) {
            u64 w = w1[o * D + i];
            a0 = fma2(x0[i], w, a0);
            a1 = fma2(x1[i], w, a1);
        }
        h0[o] = relu2(a0); h1[o] = relu2(a1);
    }
    // layer 2 + relu (write back into x0/x1)
#pragma unroll
    for (int o = 0; o < D; o++) {
        u64 b = b2[o], a0 = b, a1 = b;
#pragma unroll
        for (int i = 0; i < D; i++) {
            u64 w = w2[o * D + i];
            a0 = fma2(h0[i], w, a0);
            a1 = fma2(h1[i], w, a1);
        }
        x0[o] = relu2(a0); x1[o] = relu2(a1);
    }
    // layer 3 (linear, out dim 1)
    u64 b = b3[0], a0 = b, a1 = b;
#pragma unroll
    for (int i = 0; i < D; i++) {
        u64 w = w3[i];
        a0 = fma2(x0[i], w, a0);
        a1 = fma2(x1[i], w, a1);
    }
    float2 f0 = unpk(a0), f1 = unpk(a1);
    return f0.x + f0.y + f1.x + f1.y;
}

// Coalesced stage of TPB elements x (4*D) floats from global into shared with
// pair-interleaved layout: element e, feature i, slice s -> e*STRIDE*2 + i*4 + s.
template <int D, int STRIDE>
__device__ __forceinline__ void stage(const float* __restrict__ g, float* __restrict__ s, int tid) {
    const float4* g4 = (const float4*)g;
#pragma unroll
    for (int k = 0; k < D; k++) {
        int f = k * TPB + tid;          // float4 index, consecutive across threads
        float4 v = g4[f];
        int elem = f / D;
        int j = f - elem * D;           // float4 within element (0..D-1)
        float vv[4] = {v.x, v.y, v.z, v.w};
        float* base = s + elem * (STRIDE * 2);
#pragma unroll
        for (int c = 0; c < 4; c++) {
            int within = j * 4 + c;     // 0..4D-1, slice-major in gmem
            int sl = within / D;
            int i  = within - sl * D;
            base[i * 4 + sl] = vv[c];
        }
    }
}

__global__ __launch_bounds__(TPB, 2)
void osero_kernel(const float* __restrict__ edge, const float* __restrict__ cross,
                  const float* __restrict__ corner, const float* __restrict__ cn,
                  const float* __restrict__ eW1, const float* __restrict__ eb1,
                  const float* __restrict__ eW2, const float* __restrict__ eb2,
                  const float* __restrict__ eW3, const float* __restrict__ eb3,
                  const float* __restrict__ xW1, const float* __restrict__ xb1,
                  const float* __restrict__ xW2, const float* __restrict__ xb2,
                  const float* __restrict__ xW3, const float* __restrict__ xb3,
                  const float* __restrict__ cW1, const float* __restrict__ cb1,
                  const float* __restrict__ cW2, const float* __restrict__ cb2,
                  const float* __restrict__ cW3, const float* __restrict__ cb3,
                  const float* __restrict__ nW, const float* __restrict__ nb,
                  float* __restrict__ out) {
    __shared__ u64 swts[NWTS];
    __shared__ u64 sbuf[TPB * STRIDE10];   // 5376 u64 = 43008 B

    const int tid = threadIdx.x;
    const long long e0 = (long long)blockIdx.x * TPB;

    // ---- stage weights, duplicated into both f32x2 lanes ----
    {
        auto cp = [&](int off, const float* src, int n) {
            for (int i = tid; i < n; i += TPB) { float v = src[i]; swts[off + i] = pk2(v, v); }
        };
        cp(O_EW1, eW1, 100); cp(O_EB1, eb1, 10);
        cp(O_EW2, eW2, 100); cp(O_EB2, eb2, 10);
        cp(O_EW3, eW3, 10);  cp(O_EB3, eb3, 1);
        cp(O_XW1, xW1, 64);  cp(O_XB1, xb1, 8);
        cp(O_XW2, xW2, 64);  cp(O_XB2, xb2, 8);
        cp(O_XW3, xW3, 8);   cp(O_XB3, xb3, 1);
        cp(O_CW1, cW1, 100); cp(O_CB1, cb1, 10);
        cp(O_CW2, cW2, 100); cp(O_CB2, cb2, 10);
        cp(O_CW3, cW3, 10);  cp(O_CB3, cb3, 1);
        cp(O_NW, nW, 1);     cp(O_NB, nb, 1);
    }

    float acc;

    // ---- EDGE ----
    stage<10, STRIDE10>(edge + e0 * 40, (float*)sbuf, tid);
    __syncthreads();   // covers weights + edge staging
    acc = mlp_sum4<10>(sbuf + tid * STRIDE10,
                       swts + O_EW1, swts + O_EB1, swts + O_EW2,
                       swts + O_EB2, swts + O_EW3, swts + O_EB3);
    __syncthreads();

    // ---- CROSS ----
    stage<8, STRIDE8>(cross + e0 * 32, (float*)sbuf, tid);
    __syncthreads();
    acc += mlp_sum4<8>(sbuf + tid * STRIDE8,
                       swts + O_XW1, swts + O_XB1, swts + O_XW2,
                       swts + O_XB2, swts + O_XW3, swts + O_XB3);
    __syncthreads();

    // ---- CORNER ----
    stage<10, STRIDE10>(corner + e0 * 40, (float*)sbuf, tid);
    __syncthreads();
    acc += mlp_sum4<10>(sbuf + tid * STRIDE10,
                        swts + O_CW1, swts + O_CB1, swts + O_CW2,
                        swts + O_CB2, swts + O_CW3, swts + O_CB3);

    // ---- cn linear + output ----
    float2 nwv = unpk(swts[O_NW]);
    float2 nbv = unpk(swts[O_NB]);
    acc += cn[e0 + tid] * nwv.x + nbv.x;
    out[e0 + tid] = acc;
}

extern "C" void kernel_launch(void* const* d_in, const int* in_sizes, int n_in,
                              void* d_out, int out_size) {
    const float* edge   = (const float*)d_in[0];
    const float* cross  = (const float*)d_in[1];
    const float* corner = (const float*)d_in[2];
    const float* cn     = (const float*)d_in[3];
    const float* eW1 = (const float*)d_in[4];
    const float* eb1 = (const float*)d_in[5];
    const float* eW2 = (const float*)d_in[6];
    const float* eb2 = (const float*)d_in[7];
    const float* eW3 = (const float*)d_in[8];
    const float* eb3 = (const float*)d_in[9];
    const float* xW1 = (const float*)d_in[10];
    const float* xb1 = (const float*)d_in[11];
    const float* xW2 = (const float*)d_in[12];
    const float* xb2 = (const float*)d_in[13];
    const float* xW3 = (const float*)d_in[14];
    const float* xb3 = (const float*)d_in[15];
    const float* cW1 = (const float*)d_in[16];
    const float* cb1 = (const float*)d_in[17];
    const float* cW2 = (const float*)d_in[18];
    const float* cb2 = (const float*)d_in[19];
    const float* cW3 = (const float*)d_in[20];
    const float* cb3 = (const float*)d_in[21];
    const float* nW  = (const float*)d_in[22];
    const float* nb  = (const float*)d_in[23];

    int B = in_sizes[0] / 40;          // edge is [B,4,10]
    int blocks = B / TPB;              // 4096

    osero_kernel<<<blocks, TPB>>>(edge, cross, corner, cn,
                                  eW1, eb1, eW2, eb2, eW3, eb3,
                                  xW1, xb1, xW2, xb2, xW3, xb3,
                                  cW1, cb1, cW2, cb2, cW3, cb3,
                                  nW, nb, (float*)d_out);
}

// round 9
// speedup vs baseline: 1.0034x; 1.0034x over previous
#include <cuda_runtime.h>

typedef unsigned long long u64;

#define TPB 256
// element strides in u64 units; 21 mod 16 = 5 (coprime 16) and 17 mod 16 = 1
// -> conflict-free LDS.64 across lanes
#define STRIDE10 21   // 20 u64 data (40 floats) + 1 pad
#define STRIDE8  17   // 16 u64 data (32 floats) + 1 pad

// ---- packed f32x2 helpers ----
__device__ __forceinline__ u64 pk2(float lo, float hi) {
    u64 r; asm("mov.b64 %0,{%1,%2};" : "=l"(r) : "f"(lo), "f"(hi)); return r;
}
__device__ __forceinline__ float2 unpk(u64 v) {
    float2 f; asm("mov.b64 {%0,%1},%2;" : "=f"(f.x), "=f"(f.y) : "l"(v)); return f;
}
__device__ __forceinline__ u64 fma2(u64 a, u64 b, u64 c) {
    u64 d; asm("fma.rn.f32x2 %0,%1,%2,%3;" : "=l"(d) : "l"(a), "l"(b), "l"(c)); return d;
}
__device__ __forceinline__ u64 relu2(u64 v) {
    float2 f = unpk(v);
    return pk2(fmaxf(f.x, 0.f), fmaxf(f.y, 0.f));
}

// ---- shared weight layout (float2-duplicated), offsets in u64 units ----
#define O_EW1 0
#define O_EB1 100
#define O_EW2 110
#define O_EB2 210
#define O_EW3 220
#define O_EB3 230
#define O_XW1 231
#define O_XB1 295
#define O_XW2 303
#define O_XB2 367
#define O_XW3 375
#define O_XB3 383
#define O_CW1 384
#define O_CB1 484
#define O_CW2 494
#define O_CB2 594
#define O_CW3 604
#define O_CB3 614
#define O_NW  615
#define O_NB  616
#define NWTS  617

// 3-layer MLP over 4 slices as two f32x2 pairs, interleaved so every weight
// LDS.64 is reused by both pairs. xe points at this element's staged u64 data:
// u64 index i*2+p holds {slice 2p, slice 2p+1} for input feature i.
template <int D>
__device__ __forceinline__ float mlp_sum4(const u64* __restrict__ xe,
                                          const u64* __restrict__ w1, const u64* __restrict__ b1,
                                          const u64* __restrict__ w2, const u64* __restrict__ b2,
                                          const u64* __restrict__ w3, const u64* __restrict__ b3) {
    u64 x0[D], x1[D], h0[D], h1[D];
#pragma unroll
    for (int i = 0; i < D; i++) { x0[i] = xe[i * 2]; x1[i] = xe[i * 2 + 1]; }
    // layer 1 + relu
#pragma unroll
    for (int o = 0; o < D; o++) {
        u64 b = b1[o], a0 = b, a1 = b;
#pragma unroll
        for (int i = 0; i < D; i++) {
            u64 w = w1[o * D + i];
            a0 = fma2(x0[i], w, a0);
            a1 = fma2(x1[i], w, a1);
        }
        h0[o] = relu2(a0); h1[o] = relu2(a1);
    }
    // layer 2 + relu (write back into x0/x1)
#pragma unroll
    for (int o = 0; o < D; o++) {
        u64 b = b2[o], a0 = b, a1 = b;
#pragma unroll
        for (int i = 0; i < D; i++) {
            u64 w = w2[o * D + i];
            a0 = fma2(h0[i], w, a0);
            a1 = fma2(h1[i], w, a1);
        }
        x0[o] = relu2(a0); x1[o] = relu2(a1);
    }
    // layer 3 (linear, out dim 1)
    u64 b = b3[0], a0 = b, a1 = b;
#pragma unroll
    for (int i = 0; i < D; i++) {
        u64 w = w3[i];
        a0 = fma2(x0[i], w, a0);
        a1 = fma2(x1[i], w, a1);
    }
    float2 f0 = unpk(a0), f1 = unpk(a1);
    return f0.x + f0.y + f1.x + f1.y;
}

// Coalesced stage of TPB elements x (4*D) floats from global into shared with
// pair-interleaved layout: element e, feature i, slice s -> e*STRIDE*2 + i*4 + s.
template <int D, int STRIDE>
__device__ __forceinline__ void stage(const float* __restrict__ g, float* __restrict__ s, int tid) {
    const float4* g4 = (const float4*)g;
#pragma unroll
    for (int k = 0; k < D; k++) {
        int f = k * TPB + tid;          // float4 index, consecutive across threads
        float4 v = g4[f];
        int elem = f / D;
        int j = f - elem * D;           // float4 within element (0..D-1)
        float vv[4] = {v.x, v.y, v.z, v.w};
        float* base = s + elem * (STRIDE * 2);
#pragma unroll
        for (int c = 0; c < 4; c++) {
            int within = j * 4 + c;     // 0..4D-1, slice-major in gmem
            int sl = within / D;
            int i  = within - sl * D;
            base[i * 4 + sl] = vv[c];
        }
    }
}

__global__ __launch_bounds__(TPB, 2)
void osero_kernel(const float* __restrict__ edge, const float* __restrict__ cross,
                  const float* __restrict__ corner, const float* __restrict__ cn,
                  const float* __restrict__ eW1, const float* __restrict__ eb1,
                  const float* __restrict__ eW2, const float* __restrict__ eb2,
                  const float* __restrict__ eW3, const float* __restrict__ eb3,
                  const float* __restrict__ xW1, const float* __restrict__ xb1,
                  const float* __restrict__ xW2, const float* __restrict__ xb2,
                  const float* __restrict__ xW3, const float* __restrict__ xb3,
                  const float* __restrict__ cW1, const float* __restrict__ cb1,
                  const float* __restrict__ cW2, const float* __restrict__ cb2,
                  const float* __restrict__ cW3, const float* __restrict__ cb3,
                  const float* __restrict__ nW, const float* __restrict__ nb,
                  float* __restrict__ out) {
    __shared__ u64 swts[NWTS];
    __shared__ u64 sbuf[TPB * STRIDE10];   // 5376 u64 = 43008 B

    const int tid = threadIdx.x;
    const long long e0 = (long long)blockIdx.x * TPB;

    // ---- stage weights, duplicated into both f32x2 lanes ----
    {
        auto cp = [&](int off, const float* src, int n) {
            for (int i = tid; i < n; i += TPB) { float v = src[i]; swts[off + i] = pk2(v, v); }
        };
        cp(O_EW1, eW1, 100); cp(O_EB1, eb1, 10);
        cp(O_EW2, eW2, 100); cp(O_EB2, eb2, 10);
        cp(O_EW3, eW3, 10);  cp(O_EB3, eb3, 1);
        cp(O_XW1, xW1, 64);  cp(O_XB1, xb1, 8);
        cp(O_XW2, xW2, 64);  cp(O_XB2, xb2, 8);
        cp(O_XW3, xW3, 8);   cp(O_XB3, xb3, 1);
        cp(O_CW1, cW1, 100); cp(O_CB1, cb1, 10);
        cp(O_CW2, cW2, 100); cp(O_CB2, cb2, 10);
        cp(O_CW3, cW3, 10);  cp(O_CB3, cb3, 1);
        cp(O_NW, nW, 1);     cp(O_NB, nb, 1);
    }

    float acc;

    // ---- EDGE ----
    stage<10, STRIDE10>(edge + e0 * 40, (float*)sbuf, tid);
    __syncthreads();   // covers weights + edge staging
    acc = mlp_sum4<10>(sbuf + tid * STRIDE10,
                       swts + O_EW1, swts + O_EB1, swts + O_EW2,
                       swts + O_EB2, swts + O_EW3, swts + O_EB3);
    __syncthreads();

    // ---- CROSS ----
    stage<8, STRIDE8>(cross + e0 * 32, (float*)sbuf, tid);
    __syncthreads();
    acc += mlp_sum4<8>(sbuf + tid * STRIDE8,
                       swts + O_XW1, swts + O_XB1, swts + O_XW2,
                       swts + O_XB2, swts + O_XW3, swts + O_XB3);
    __syncthreads();

    // ---- CORNER ----
    stage<10, STRIDE10>(corner + e0 * 40, (float*)sbuf, tid);
    __syncthreads();
    acc += mlp_sum4<10>(sbuf + tid * STRIDE10,
                        swts + O_CW1, swts + O_CB1, swts + O_CW2,
                        swts + O_CB2, swts + O_CW3, swts + O_CB3);

    // ---- cn linear + output ----
    float2 nwv = unpk(swts[O_NW]);
    float2 nbv = unpk(swts[O_NB]);
    acc += cn[e0 + tid] * nwv.x + nbv.x;
    out[e0 + tid] = acc;
}

extern "C" void kernel_launch(void* const* d_in, const int* in_sizes, int n_in,
                              void* d_out, int out_size) {
    const float* edge   = (const float*)d_in[0];
    const float* cross  = (const float*)d_in[1];
    const float* corner = (const float*)d_in[2];
    const float* cn     = (const float*)d_in[3];
    const float* eW1 = (const float*)d_in[4];
    const float* eb1 = (const float*)d_in[5];
    const float* eW2 = (const float*)d_in[6];
    const float* eb2 = (const float*)d_in[7];
    const float* eW3 = (const float*)d_in[8];
    const float* eb3 = (const float*)d_in[9];
    const float* xW1 = (const float*)d_in[10];
    const float* xb1 = (const float*)d_in[11];
    const float* xW2 = (const float*)d_in[12];
    const float* xb2 = (const float*)d_in[13];
    const float* xW3 = (const float*)d_in[14];
    const float* xb3 = (const float*)d_in[15];
    const float* cW1 = (const float*)d_in[16];
    const float* cb1 = (const float*)d_in[17];
    const float* cW2 = (const float*)d_in[18];
    const float* cb2 = (const float*)d_in[19];
    const float* cW3 = (const float*)d_in[20];
    const float* cb3 = (const float*)d_in[21];
    const float* nW  = (const float*)d_in[22];
    const float* nb  = (const float*)d_in[23];

    int B = in_sizes[0] / 40;          // edge is [B,4,10]
    int blocks = B / TPB;              // 4096

    osero_kernel<<<blocks, TPB>>>(edge, cross, corner, cn,
                                  eW1, eb1, eW2, eb2, eW3, eb3,
                                  xW1, xb1, xW2, xb2, xW3, xb3,
                                  cW1, cb1, cW2, cb2, cW3, cb3,
                                  nW, nb, (float*)d_out);
}

// round 10
// speedup vs baseline: 1.1869x; 1.1828x over previous
#include <cuda_runtime.h>

typedef unsigned long long u64;

#define TPB 128
// element strides in u64 units; 21 mod 16 = 5 (coprime 16) and 17 mod 16 = 1
// -> conflict-free LDS.64 across 16-lane phases
#define STRIDE10 21   // 20 u64 data (40 floats) + 1 pad
#define STRIDE8  17   // 16 u64 data (32 floats) + 1 pad

// ---- packed f32x2 helpers ----
__device__ __forceinline__ u64 pk2(float lo, float hi) {
    u64 r; asm("mov.b64 %0,{%1,%2};" : "=l"(r) : "f"(lo), "f"(hi)); return r;
}
__device__ __forceinline__ float2 unpk(u64 v) {
    float2 f; asm("mov.b64 {%0,%1},%2;" : "=f"(f.x), "=f"(f.y) : "l"(v)); return f;
}
__device__ __forceinline__ u64 fma2(u64 a, u64 b, u64 c) {
    u64 d; asm("fma.rn.f32x2 %0,%1,%2,%3;" : "=l"(d) : "l"(a), "l"(b), "l"(c)); return d;
}
__device__ __forceinline__ u64 relu2(u64 v) {
    float2 f = unpk(v);
    return pk2(fmaxf(f.x, 0.f), fmaxf(f.y, 0.f));
}

// ---- shared layout (u64 units) ----
// weights (float2-duplicated)
#define O_EW1 0
#define O_EB1 100
#define O_EW2 110
#define O_EB2 210
#define O_EW3 220
#define O_EB3 230
#define O_XW1 231
#define O_XB1 295
#define O_XW2 303
#define O_XB2 367
#define O_XW3 375
#define O_XB3 383
#define O_CW1 384
#define O_CB1 484
#define O_CW2 494
#define O_CB2 594
#define O_CW3 604
#define O_CB3 614
#define O_NW  615
#define O_NB  616
#define NWTS  617
// staged input buffers (all resident simultaneously -> ONE barrier)
#define O_EDGE   624
#define O_CROSS  (O_EDGE + TPB * STRIDE10)            // 624 + 2688 = 3312
#define O_CORNER (O_CROSS + TPB * STRIDE8)            // 3312 + 2176 = 5488
#define SMEM_U64 (O_CORNER + TPB * STRIDE10)          // 5488 + 2688 = 8176
#define SMEM_BYTES (SMEM_U64 * 8)                     // 65408

// 3-layer MLP over 4 slices as two f32x2 pairs, interleaved so every weight
// LDS.64 feeds both pairs. xe: u64 index i*2+p = {slice 2p, slice 2p+1}, feature i.
template <int D>
__device__ __forceinline__ float mlp_sum4(const u64* __restrict__ xe,
                                          const u64* __restrict__ w1, const u64* __restrict__ b1,
                                          const u64* __restrict__ w2, const u64* __restrict__ b2,
                                          const u64* __restrict__ w3, const u64* __restrict__ b3) {
    u64 x0[D], x1[D], h0[D], h1[D];
#pragma unroll
    for (int i = 0; i < D; i++) { x0[i] = xe[i * 2]; x1[i] = xe[i * 2 + 1]; }
#pragma unroll
    for (int o = 0; o < D; o++) {
        u64 b = b1[o], a0 = b, a1 = b;
#pragma unroll
        for (int i = 0; i < D; i++) {
            u64 w = w1[o * D + i];
            a0 = fma2(x0[i], w, a0);
            a1 = fma2(x1[i], w, a1);
        }
        h0[o] = relu2(a0); h1[o] = relu2(a1);
    }
#pragma unroll
    for (int o = 0; o < D; o++) {
        u64 b = b2[o], a0 = b, a1 = b;
#pragma unroll
        for (int i = 0; i < D; i++) {
            u64 w = w2[o * D + i];
            a0 = fma2(h0[i], w, a0);
            a1 = fma2(h1[i], w, a1);
        }
        x0[o] = relu2(a0); x1[o] = relu2(a1);
    }
    u64 b = b3[0], a0 = b, a1 = b;
#pragma unroll
    for (int i = 0; i < D; i++) {
        u64 w = w3[i];
        a0 = fma2(x0[i], w, a0);
        a1 = fma2(x1[i], w, a1);
    }
    float2 f0 = unpk(a0), f1 = unpk(a1);
    return f0.x + f0.y + f1.x + f1.y;
}

// Coalesced stage of TPB elements x (4*D) floats from global into shared with
// pair-interleaved layout: element e, feature i, slice s -> e*STRIDE*2 + i*4 + s (floats).
template <int D, int STRIDE>
__device__ __forceinline__ void stage(const float* __restrict__ g, float* __restrict__ s, int tid) {
    const float4* g4 = (const float4*)g;
#pragma unroll
    for (int k = 0; k < D; k++) {
        int f = k * TPB + tid;          // float4 index, consecutive across threads
        float4 v = g4[f];
        int elem = f / D;
        int j = f - elem * D;           // float4 within element (0..D-1)
        float vv[4] = {v.x, v.y, v.z, v.w};
        float* base = s + elem * (STRIDE * 2);
#pragma unroll
        for (int c = 0; c < 4; c++) {
            int within = j * 4 + c;     // 0..4D-1, slice-major in gmem
            int sl = within / D;
            int i  = within - sl * D;
            base[i * 4 + sl] = vv[c];
        }
    }
}

__global__ __launch_bounds__(TPB, 3)
void osero_kernel(const float* __restrict__ edge, const float* __restrict__ cross,
                  const float* __restrict__ corner, const float* __restrict__ cn,
                  const float* __restrict__ eW1, const float* __restrict__ eb1,
                  const float* __restrict__ eW2, const float* __restrict__ eb2,
                  const float* __restrict__ eW3, const float* __restrict__ eb3,
                  const float* __restrict__ xW1, const float* __restrict__ xb1,
                  const float* __restrict__ xW2, const float* __restrict__ xb2,
                  const float* __restrict__ xW3, const float* __restrict__ xb3,
                  const float* __restrict__ cW1, const float* __restrict__ cb1,
                  const float* __restrict__ cW2, const float* __restrict__ cb2,
                  const float* __restrict__ cW3, const float* __restrict__ cb3,
                  const float* __restrict__ nW, const float* __restrict__ nb,
                  float* __restrict__ out) {
    extern __shared__ u64 dsm[];
    u64* swts = dsm;

    const int tid = threadIdx.x;
    const long long e0 = (long long)blockIdx.x * TPB;

    // ---- stage ALL inputs first: 30 LDG.128 in flight per thread ----
    stage<10, STRIDE10>(edge   + e0 * 40, (float*)(dsm + O_EDGE),   tid);
    stage<8,  STRIDE8 >(cross  + e0 * 32, (float*)(dsm + O_CROSS),  tid);
    stage<10, STRIDE10>(corner + e0 * 40, (float*)(dsm + O_CORNER), tid);
    const float cnv = cn[e0 + tid];

    // ---- stage weights, duplicated into both f32x2 lanes ----
    {
        auto cp = [&](int off, const float* src, int n) {
            for (int i = tid; i < n; i += TPB) { float v = src[i]; swts[off + i] = pk2(v, v); }
        };
        cp(O_EW1, eW1, 100); cp(O_EB1, eb1, 10);
        cp(O_EW2, eW2, 100); cp(O_EB2, eb2, 10);
        cp(O_EW3, eW3, 10);  cp(O_EB3, eb3, 1);
        cp(O_XW1, xW1, 64);  cp(O_XB1, xb1, 8);
        cp(O_XW2, xW2, 64);  cp(O_XB2, xb2, 8);
        cp(O_XW3, xW3, 8);   cp(O_XB3, xb3, 1);
        cp(O_CW1, cW1, 100); cp(O_CB1, cb1, 10);
        cp(O_CW2, cW2, 100); cp(O_CB2, cb2, 10);
        cp(O_CW3, cW3, 10);  cp(O_CB3, cb3, 1);
        cp(O_NW, nW, 1);     cp(O_NB, nb, 1);
    }

    __syncthreads();   // the ONLY barrier

    float acc = mlp_sum4<10>(dsm + O_EDGE + tid * STRIDE10,
                             swts + O_EW1, swts + O_EB1, swts + O_EW2,
                             swts + O_EB2, swts + O_EW3, swts + O_EB3);
    acc += mlp_sum4<8>(dsm + O_CROSS + tid * STRIDE8,
                       swts + O_XW1, swts + O_XB1, swts + O_XW2,
                       swts + O_XB2, swts + O_XW3, swts + O_XB3);
    acc += mlp_sum4<10>(dsm + O_CORNER + tid * STRIDE10,
                        swts + O_CW1, swts + O_CB1, swts + O_CW2,
                        swts + O_CB2, swts + O_CW3, swts + O_CB3);

    float2 nwv = unpk(swts[O_NW]);
    float2 nbv = unpk(swts[O_NB]);
    acc += cnv * nwv.x + nbv.x;
    out[e0 + tid] = acc;
}

extern "C" void kernel_launch(void* const* d_in, const int* in_sizes, int n_in,
                              void* d_out, int out_size) {
    const float* edge   = (const float*)d_in[0];
    const float* cross  = (const float*)d_in[1];
    const float* corner = (const float*)d_in[2];
    const float* cn     = (const float*)d_in[3];
    const float* eW1 = (const float*)d_in[4];
    const float* eb1 = (const float*)d_in[5];
    const float* eW2 = (const float*)d_in[6];
    const float* eb2 = (const float*)d_in[7];
    const float* eW3 = (const float*)d_in[8];
    const float* eb3 = (const float*)d_in[9];
    const float* xW1 = (const float*)d_in[10];
    const float* xb1 = (const float*)d_in[11];
    const float* xW2 = (const float*)d_in[12];
    const float* xb2 = (const float*)d_in[13];
    const float* xW3 = (const float*)d_in[14];
    const float* xb3 = (const float*)d_in[15];
    const float* cW1 = (const float*)d_in[16];
    const float* cb1 = (const float*)d_in[17];
    const float* cW2 = (const float*)d_in[18];
    const float* cb2 = (const float*)d_in[19];
    const float* cW3 = (const float*)d_in[20];
    const float* cb3 = (const float*)d_in[21];
    const float* nW  = (const float*)d_in[22];
    const float* nb  = (const float*)d_in[23];

    int B = in_sizes[0] / 40;          // edge is [B,4,10]
    int blocks = B / TPB;              // 8192

    cudaFuncSetAttribute(osero_kernel,
                         cudaFuncAttributeMaxDynamicSharedMemorySize, SMEM_BYTES);

    osero_kernel<<<blocks, TPB, SMEM_BYTES>>>(edge, cross, corner, cn,
                                  eW1, eb1, eW2, eb2, eW3, eb3,
                                  xW1, xb1, xW2, xb2, xW3, xb3,
                                  cW1, cb1, cW2, cb2, cW3, cb3,
                                  nW, nb, (float*)d_out);
}

// round 11
// speedup vs baseline: 1.1896x; 1.0023x over previous
#include <cuda_runtime.h>

typedef unsigned long long u64;

#define TPB 128
// element strides in u64 units; 21 mod 16 = 5 (coprime 16) and 17 mod 16 = 1
// -> conflict-free LDS.64 across 16-lane phases
#define STRIDE10 21   // 20 u64 data (40 floats) + 1 pad
#define STRIDE8  17   // 16 u64 data (32 floats) + 1 pad

// ---- packed f32x2 helpers ----
__device__ __forceinline__ u64 pk2(float lo, float hi) {
    u64 r; asm("mov.b64 %0,{%1,%2};" : "=l"(r) : "f"(lo), "f"(hi)); return r;
}
__device__ __forceinline__ float2 unpk(u64 v) {
    float2 f; asm("mov.b64 {%0,%1},%2;" : "=f"(f.x), "=f"(f.y) : "l"(v)); return f;
}
__device__ __forceinline__ u64 fma2(u64 a, u64 b, u64 c) {
    u64 d; asm("fma.rn.f32x2 %0,%1,%2,%3;" : "=l"(d) : "l"(a), "l"(b), "l"(c)); return d;
}
__device__ __forceinline__ u64 relu2(u64 v) {
    float2 f = unpk(v);
    return pk2(fmaxf(f.x, 0.f), fmaxf(f.y, 0.f));
}

// ---- shared layout (u64 units) ----
// weights (float2-duplicated)
#define O_EW1 0
#define O_EB1 100
#define O_EW2 110
#define O_EB2 210
#define O_EW3 220
#define O_EB3 230
#define O_XW1 231
#define O_XB1 295
#define O_XW2 303
#define O_XB2 367
#define O_XW3 375
#define O_XB3 383
#define O_CW1 384
#define O_CB1 484
#define O_CW2 494
#define O_CB2 594
#define O_CW3 604
#define O_CB3 614
#define O_NW  615
#define O_NB  616
#define NWTS  617
// staged input buffers (all resident simultaneously -> ONE barrier)
#define O_EDGE   624
#define O_CROSS  (O_EDGE + TPB * STRIDE10)            // 624 + 2688 = 3312
#define O_CORNER (O_CROSS + TPB * STRIDE8)            // 3312 + 2176 = 5488
#define SMEM_U64 (O_CORNER + TPB * STRIDE10)          // 5488 + 2688 = 8176
#define SMEM_BYTES (SMEM_U64 * 8)                     // 65408

// 3-layer MLP over 4 slices as two f32x2 pairs, interleaved so every weight
// LDS.64 feeds both pairs. xe: u64 index i*2+p = {slice 2p, slice 2p+1}, feature i.
template <int D>
__device__ __forceinline__ float mlp_sum4(const u64* __restrict__ xe,
                                          const u64* __restrict__ w1, const u64* __restrict__ b1,
                                          const u64* __restrict__ w2, const u64* __restrict__ b2,
                                          const u64* __restrict__ w3, const u64* __restrict__ b3) {
    u64 x0[D], x1[D], h0[D], h1[D];
#pragma unroll
    for (int i = 0; i < D; i++) { x0[i] = xe[i * 2]; x1[i] = xe[i * 2 + 1]; }
#pragma unroll
    for (int o = 0; o < D; o++) {
        u64 b = b1[o], a0 = b, a1 = b;
#pragma unroll
        for (int i = 0; i < D; i++) {
            u64 w = w1[o * D + i];
            a0 = fma2(x0[i], w, a0);
            a1 = fma2(x1[i], w, a1);
        }
        h0[o] = relu2(a0); h1[o] = relu2(a1);
    }
#pragma unroll
    for (int o = 0; o < D; o++) {
        u64 b = b2[o], a0 = b, a1 = b;
#pragma unroll
        for (int i = 0; i < D; i++) {
            u64 w = w2[o * D + i];
            a0 = fma2(h0[i], w, a0);
            a1 = fma2(h1[i], w, a1);
        }
        x0[o] = relu2(a0); x1[o] = relu2(a1);
    }
    u64 b = b3[0], a0 = b, a1 = b;
#pragma unroll
    for (int i = 0; i < D; i++) {
        u64 w = w3[i];
        a0 = fma2(x0[i], w, a0);
        a1 = fma2(x1[i], w, a1);
    }
    float2 f0 = unpk(a0), f1 = unpk(a1);
    return f0.x + f0.y + f1.x + f1.y;
}

// Coalesced stage of TPB elements x (4*D) floats from global into shared with
// pair-interleaved layout: element e, feature i, slice s -> e*STRIDE*2 + i*4 + s (floats).
template <int D, int STRIDE>
__device__ __forceinline__ void stage(const float* __restrict__ g, float* __restrict__ s, int tid) {
    const float4* g4 = (const float4*)g;
#pragma unroll
    for (int k = 0; k < D; k++) {
        int f = k * TPB + tid;          // float4 index, consecutive across threads
        float4 v = g4[f];
        int elem = f / D;
        int j = f - elem * D;           // float4 within element (0..D-1)
        float vv[4] = {v.x, v.y, v.z, v.w};
        float* base = s + elem * (STRIDE * 2);
#pragma unroll
        for (int c = 0; c < 4; c++) {
            int within = j * 4 + c;     // 0..4D-1, slice-major in gmem
            int sl = within / D;
            int i  = within - sl * D;
            base[i * 4 + sl] = vv[c];
        }
    }
}

__global__ __launch_bounds__(TPB, 3)
void osero_kernel(const float* __restrict__ edge, const float* __restrict__ cross,
                  const float* __restrict__ corner, const float* __restrict__ cn,
                  const float* __restrict__ eW1, const float* __restrict__ eb1,
                  const float* __restrict__ eW2, const float* __restrict__ eb2,
                  const float* __restrict__ eW3, const float* __restrict__ eb3,
                  const float* __restrict__ xW1, const float* __restrict__ xb1,
                  const float* __restrict__ xW2, const float* __restrict__ xb2,
                  const float* __restrict__ xW3, const float* __restrict__ xb3,
                  const float* __restrict__ cW1, const float* __restrict__ cb1,
                  const float* __restrict__ cW2, const float* __restrict__ cb2,
                  const float* __restrict__ cW3, const float* __restrict__ cb3,
                  const float* __restrict__ nW, const float* __restrict__ nb,
                  float* __restrict__ out) {
    extern __shared__ u64 dsm[];
    u64* swts = dsm;

    const int tid = threadIdx.x;
    const long long e0 = (long long)blockIdx.x * TPB;

    // ---- stage ALL inputs first: 30 LDG.128 in flight per thread ----
    stage<10, STRIDE10>(edge   + e0 * 40, (float*)(dsm + O_EDGE),   tid);
    stage<8,  STRIDE8 >(cross  + e0 * 32, (float*)(dsm + O_CROSS),  tid);
    stage<10, STRIDE10>(corner + e0 * 40, (float*)(dsm + O_CORNER), tid);
    const float cnv = cn[e0 + tid];

    // ---- stage weights, duplicated into both f32x2 lanes ----
    {
        auto cp = [&](int off, const float* src, int n) {
            for (int i = tid; i < n; i += TPB) { float v = src[i]; swts[off + i] = pk2(v, v); }
        };
        cp(O_EW1, eW1, 100); cp(O_EB1, eb1, 10);
        cp(O_EW2, eW2, 100); cp(O_EB2, eb2, 10);
        cp(O_EW3, eW3, 10);  cp(O_EB3, eb3, 1);
        cp(O_XW1, xW1, 64);  cp(O_XB1, xb1, 8);
        cp(O_XW2, xW2, 64);  cp(O_XB2, xb2, 8);
        cp(O_XW3, xW3, 8);   cp(O_XB3, xb3, 1);
        cp(O_CW1, cW1, 100); cp(O_CB1, cb1, 10);
        cp(O_CW2, cW2, 100); cp(O_CB2, cb2, 10);
        cp(O_CW3, cW3, 10);  cp(O_CB3, cb3, 1);
        cp(O_NW, nW, 1);     cp(O_NB, nb, 1);
    }

    __syncthreads();   // the ONLY barrier

    float acc = mlp_sum4<10>(dsm + O_EDGE + tid * STRIDE10,
                             swts + O_EW1, swts + O_EB1, swts + O_EW2,
                             swts + O_EB2, swts + O_EW3, swts + O_EB3);
    acc += mlp_sum4<8>(dsm + O_CROSS + tid * STRIDE8,
                       swts + O_XW1, swts + O_XB1, swts + O_XW2,
                       swts + O_XB2, swts + O_XW3, swts + O_XB3);
    acc += mlp_sum4<10>(dsm + O_CORNER + tid * STRIDE10,
                        swts + O_CW1, swts + O_CB1, swts + O_CW2,
                        swts + O_CB2, swts + O_CW3, swts + O_CB3);

    float2 nwv = unpk(swts[O_NW]);
    float2 nbv = unpk(swts[O_NB]);
    acc += cnv * nwv.x + nbv.x;
    out[e0 + tid] = acc;
}

extern "C" void kernel_launch(void* const* d_in, const int* in_sizes, int n_in,
                              void* d_out, int out_size) {
    const float* edge   = (const float*)d_in[0];
    const float* cross  = (const float*)d_in[1];
    const float* corner = (const float*)d_in[2];
    const float* cn     = (const float*)d_in[3];
    const float* eW1 = (const float*)d_in[4];
    const float* eb1 = (const float*)d_in[5];
    const float* eW2 = (const float*)d_in[6];
    const float* eb2 = (const float*)d_in[7];
    const float* eW3 = (const float*)d_in[8];
    const float* eb3 = (const float*)d_in[9];
    const float* xW1 = (const float*)d_in[10];
    const float* xb1 = (const float*)d_in[11];
    const float* xW2 = (const float*)d_in[12];
    const float* xb2 = (const float*)d_in[13];
    const float* xW3 = (const float*)d_in[14];
    const float* xb3 = (const float*)d_in[15];
    const float* cW1 = (const float*)d_in[16];
    const float* cb1 = (const float*)d_in[17];
    const float* cW2 = (const float*)d_in[18];
    const float* cb2 = (const float*)d_in[19];
    const float* cW3 = (const float*)d_in[20];
    const float* cb3 = (const float*)d_in[21];
    const float* nW  = (const float*)d_in[22];
    const float* nb  = (const float*)d_in[23];

    int B = in_sizes[0] / 40;          // edge is [B,4,10]
    int blocks = B / TPB;              // 8192

    cudaFuncSetAttribute(osero_kernel,
                         cudaFuncAttributeMaxDynamicSharedMemorySize, SMEM_BYTES);

    osero_kernel<<<blocks, TPB, SMEM_BYTES>>>(edge, cross, corner, cn,
                                  eW1, eb1, eW2, eb2, eW3, eb3,
                                  xW1, xb1, xW2, xb2, xW3, xb3,
                                  cW1, cb1, cW2, cb2, cW3, cb3,
                                  nW, nb, (float*)d_out);
}